// round 1
// baseline (speedup 1.0000x reference)
#include <cuda_runtime.h>
#include <math.h>

// Problem constants
#define NNODE 50000
#define NEDGE 800000
#define FIN 128
#define COUT 128   // NH*FOUT
#define NH 4

// ---------------- device scratch (no allocations allowed) ----------------
__device__ float  g_src_proj[NNODE * COUT];        // 25.6 MB
__device__ float4 g_scores_src[NNODE];             // per-node, 4 heads
__device__ float4 g_scores_trg[NNODE];
__device__ float4 g_denom[NNODE];
__device__ int    g_count[NNODE];
__device__ int    g_cursor[NNODE];
__device__ int    g_offsets[NNODE + 1];
__device__ int    g_sorted_si[NEDGE];
__device__ float4 g_sorted_exp[NEDGE];
__device__ float  g_Vt[FIN * NH];                  // folded Wt @ a_trg

// ---------------- kernels ----------------

__global__ void zero_kernel() {
    int i = blockIdx.x * blockDim.x + threadIdx.x;
    int stride = gridDim.x * blockDim.x;
    float* dn = (float*)g_denom;
    for (int k = i; k < NNODE * 4; k += stride) dn[k] = 0.0f;
    for (int k = i; k < NNODE; k += stride) { g_count[k] = 0; g_cursor[k] = 0; }
}

// Vt[f,h] = sum_j Wt[f, h*32+j] * a_trg[h, j]
__global__ void fold_kernel(const float* __restrict__ Wt,
                            const float* __restrict__ a_trg) {
    int f = threadIdx.x;  // 128 threads
    #pragma unroll
    for (int h = 0; h < NH; h++) {
        float s = 0.0f;
        #pragma unroll
        for (int j = 0; j < 32; j++)
            s += Wt[f * COUT + h * 32 + j] * a_trg[h * 32 + j];
        g_Vt[f * NH + h] = s;
    }
}

// scores_trg = trg @ Vt   (warp per node)
__global__ void strg_kernel(const float* __restrict__ trg) {
    __shared__ float Vsh[FIN * NH];
    for (int i = threadIdx.x; i < FIN * NH; i += blockDim.x) Vsh[i] = g_Vt[i];
    __syncthreads();

    int gwarp = (blockIdx.x * blockDim.x + threadIdx.x) >> 5;
    int lane = threadIdx.x & 31;
    if (gwarp >= NNODE) return;

    float4 xv = ((const float4*)(trg + (size_t)gwarp * FIN))[lane];
    int f0 = lane * 4;
    float a0, a1, a2, a3;
    a0 = xv.x * Vsh[(f0+0)*4+0] + xv.y * Vsh[(f0+1)*4+0] + xv.z * Vsh[(f0+2)*4+0] + xv.w * Vsh[(f0+3)*4+0];
    a1 = xv.x * Vsh[(f0+0)*4+1] + xv.y * Vsh[(f0+1)*4+1] + xv.z * Vsh[(f0+2)*4+1] + xv.w * Vsh[(f0+3)*4+1];
    a2 = xv.x * Vsh[(f0+0)*4+2] + xv.y * Vsh[(f0+1)*4+2] + xv.z * Vsh[(f0+2)*4+2] + xv.w * Vsh[(f0+3)*4+2];
    a3 = xv.x * Vsh[(f0+0)*4+3] + xv.y * Vsh[(f0+1)*4+3] + xv.z * Vsh[(f0+2)*4+3] + xv.w * Vsh[(f0+3)*4+3];
    #pragma unroll
    for (int o = 16; o > 0; o >>= 1) {
        a0 += __shfl_xor_sync(0xffffffffu, a0, o);
        a1 += __shfl_xor_sync(0xffffffffu, a1, o);
        a2 += __shfl_xor_sync(0xffffffffu, a2, o);
        a3 += __shfl_xor_sync(0xffffffffu, a3, o);
    }
    if (lane == 0) g_scores_trg[gwarp] = make_float4(a0, a1, a2, a3);
}

// src_proj = src @ Ws, fused scores_src epilogue. Warp per node, Ws in smem.
__global__ void proj_kernel(const float* __restrict__ src,
                            const float* __restrict__ Ws,
                            const float* __restrict__ a_src) {
    extern __shared__ float sh[];
    float* Wsh = sh;                    // 128*128
    float* ash = sh + FIN * COUT;       // 128
    float* xsh = ash + COUT;            // warpsPerBlock * 128

    // cooperative load of Ws (float4)
    {
        const float4* w4 = (const float4*)Ws;
        float4* s4 = (float4*)Wsh;
        for (int i = threadIdx.x; i < FIN * COUT / 4; i += blockDim.x) s4[i] = w4[i];
        for (int i = threadIdx.x; i < COUT; i += blockDim.x) ash[i] = a_src[i];
    }
    __syncthreads();

    int lane = threadIdx.x & 31;
    int warpInBlock = threadIdx.x >> 5;
    float* myx = xsh + warpInBlock * FIN;
    int gwarp = (blockIdx.x * blockDim.x + threadIdx.x) >> 5;
    int warpStride = (gridDim.x * blockDim.x) >> 5;

    for (int n = gwarp; n < NNODE; n += warpStride) {
        float4 xv = ((const float4*)(src + (size_t)n * FIN))[lane];
        ((float4*)myx)[lane] = xv;
        __syncwarp();

        float acc0 = 0.f, acc1 = 0.f, acc2 = 0.f, acc3 = 0.f;
        #pragma unroll
        for (int f = 0; f < FIN; f++) {
            float xf = myx[f];
            float4 w = ((const float4*)(Wsh + f * COUT))[lane];
            acc0 += xf * w.x; acc1 += xf * w.y; acc2 += xf * w.z; acc3 += xf * w.w;
        }
        ((float4*)(g_src_proj + (size_t)n * COUT))[lane] = make_float4(acc0, acc1, acc2, acc3);

        // scores_src: col = lane*4+j, head = lane>>3, f_in_head = (lane&7)*4+j
        int h = lane >> 3;
        int fi = (lane & 7) * 4;
        float p = acc0 * ash[h * 32 + fi + 0] + acc1 * ash[h * 32 + fi + 1]
                + acc2 * ash[h * 32 + fi + 2] + acc3 * ash[h * 32 + fi + 3];
        p += __shfl_xor_sync(0xffffffffu, p, 4);
        p += __shfl_xor_sync(0xffffffffu, p, 2);
        p += __shfl_xor_sync(0xffffffffu, p, 1);
        if ((lane & 7) == 0) ((float*)g_scores_src)[n * 4 + h] = p;
        __syncwarp();
    }
}

__device__ __forceinline__ float lrelu_exp(float s) {
    float l = s > 0.0f ? s : 0.2f * s;
    return expf(l);
}

// pass 1: per-edge exp -> denom (atomic), degree counts
__global__ void edge1_kernel(const int* __restrict__ ei) {
    int e = blockIdx.x * blockDim.x + threadIdx.x;
    if (e >= NEDGE) return;
    int si = ei[e];
    int ti = ei[NEDGE + e];
    float4 ss = g_scores_src[si];
    float4 st = g_scores_trg[ti];
    float e0 = lrelu_exp(ss.x + st.x);
    float e1 = lrelu_exp(ss.y + st.y);
    float e2 = lrelu_exp(ss.z + st.z);
    float e3 = lrelu_exp(ss.w + st.w);
    float* dn = (float*)&g_denom[ti];
    atomicAdd(dn + 0, e0);
    atomicAdd(dn + 1, e1);
    atomicAdd(dn + 2, e2);
    atomicAdd(dn + 3, e3);
    atomicAdd(&g_count[ti], 1);
}

// single-block exclusive scan of g_count -> g_offsets
__global__ void scan_kernel() {
    __shared__ int sh[1024];
    __shared__ int carry;
    int tid = threadIdx.x;
    if (tid == 0) { carry = 0; g_offsets[0] = 0; }
    __syncthreads();
    for (int base = 0; base < NNODE; base += 1024) {
        int v = (base + tid < NNODE) ? g_count[base + tid] : 0;
        sh[tid] = v;
        __syncthreads();
        #pragma unroll
        for (int off = 1; off < 1024; off <<= 1) {
            int t = (tid >= off) ? sh[tid - off] : 0;
            __syncthreads();
            sh[tid] += t;
            __syncthreads();
        }
        int incl = sh[tid];
        if (base + tid < NNODE) g_offsets[base + tid + 1] = carry + incl;
        __syncthreads();
        if (tid == 1023) carry += incl;
        __syncthreads();
    }
}

// pass 2: bucket-scatter edges into CSR order, store (si, exp4)
__global__ void edge2_kernel(const int* __restrict__ ei) {
    int e = blockIdx.x * blockDim.x + threadIdx.x;
    if (e >= NEDGE) return;
    int si = ei[e];
    int ti = ei[NEDGE + e];
    float4 ss = g_scores_src[si];
    float4 st = g_scores_trg[ti];
    float4 ex;
    ex.x = lrelu_exp(ss.x + st.x);
    ex.y = lrelu_exp(ss.y + st.y);
    ex.z = lrelu_exp(ss.z + st.z);
    ex.w = lrelu_exp(ss.w + st.w);
    int pos = g_offsets[ti] + atomicAdd(&g_cursor[ti], 1);
    g_sorted_si[pos] = si;
    g_sorted_exp[pos] = ex;
}

// aggregation: warp per target node, gather src_proj rows from L2
__global__ void agg_kernel(float* __restrict__ out) {
    int gwarp = (blockIdx.x * blockDim.x + threadIdx.x) >> 5;
    int lane = threadIdx.x & 31;
    if (gwarp >= NNODE) return;

    int s = g_offsets[gwarp];
    int e2 = g_offsets[gwarp + 1];
    float a0 = 0.f, a1 = 0.f, a2 = 0.f, a3 = 0.f;

    for (int i = s; i < e2; i++) {
        int si = g_sorted_si[i];
        float4 ex = g_sorted_exp[i];
        const float* sp = g_src_proj + (size_t)si * COUT;
        a0 += ex.x * sp[lane];
        a1 += ex.y * sp[32 + lane];
        a2 += ex.z * sp[64 + lane];
        a3 += ex.w * sp[96 + lane];
    }

    float4 dn = g_denom[gwarp];
    float r0 = 1.0f / (dn.x + 1e-16f);
    float r1 = 1.0f / (dn.y + 1e-16f);
    float r2 = 1.0f / (dn.z + 1e-16f);
    float r3 = 1.0f / (dn.w + 1e-16f);

    float* o = out + (size_t)gwarp * COUT;
    o[lane]      = a0 * r0;
    o[32 + lane] = a1 * r1;
    o[64 + lane] = a2 * r2;
    o[96 + lane] = a3 * r3;
}

// ---------------- launch ----------------

extern "C" void kernel_launch(void* const* d_in, const int* in_sizes, int n_in,
                              void* d_out, int out_size) {
    const float* trg   = (const float*)d_in[0];
    const float* src   = (const float*)d_in[1];
    const int*   ei    = (const int*)d_in[2];
    const float* Wt    = (const float*)d_in[3];
    const float* Ws    = (const float*)d_in[4];
    const float* a_src = (const float*)d_in[5];
    const float* a_trg = (const float*)d_in[6];
    float* out = (float*)d_out;

    // proj kernel smem: Ws (64KB) + a_src (512B) + 8 warps * 128 floats (4KB)
    const int PROJ_BLOCK = 256;
    const int PROJ_WARPS = PROJ_BLOCK / 32;
    size_t proj_smem = (size_t)(FIN * COUT + COUT + PROJ_WARPS * FIN) * sizeof(float);
    cudaFuncSetAttribute(proj_kernel, cudaFuncAttributeMaxDynamicSharedMemorySize,
                         (int)proj_smem);

    zero_kernel<<<256, 256>>>();
    fold_kernel<<<1, 128>>>(Wt, a_trg);

    {
        int warps = NNODE;
        int blocks = (warps * 32 + 255) / 256;
        strg_kernel<<<blocks, 256>>>(trg);
    }

    proj_kernel<<<444, PROJ_BLOCK, proj_smem>>>(src, Ws, a_src);

    {
        int blocks = (NEDGE + 255) / 256;
        edge1_kernel<<<blocks, 256>>>(ei);
    }

    scan_kernel<<<1, 1024>>>();

    {
        int blocks = (NEDGE + 255) / 256;
        edge2_kernel<<<blocks, 256>>>(ei);
    }

    {
        int warps = NNODE;
        int blocks = (warps * 32 + 255) / 256;
        agg_kernel<<<blocks, 256>>>(out);
    }
}

// round 2
// speedup vs baseline: 1.8936x; 1.8936x over previous
#include <cuda_runtime.h>
#include <math.h>

// Problem constants
#define NNODE 50000
#define NEDGE 800000
#define FIN 128
#define COUT 128   // NH*FOUT
#define NH 4

#define PROJ_WARPS 8
#define NPW 8            // nodes per warp per iteration
#define SCAN_BLK 1024
#define NSCAN_BLKS ((NNODE + SCAN_BLK - 1) / SCAN_BLK)   // 49

// ---------------- device scratch (no allocations allowed) ----------------
__device__ float  g_src_proj[NNODE * COUT];        // 25.6 MB
__device__ float4 g_scores_src[NNODE];
__device__ float4 g_scores_trg[NNODE];
__device__ int    g_count[NNODE];
__device__ int    g_offsets[NNODE + 1];
__device__ int    g_blocksum[NSCAN_BLKS];
__device__ int    g_blockcarry[NSCAN_BLKS];
__device__ int    g_edge_rank[NEDGE];
__device__ float4 g_edge_exp[NEDGE];               // 12.8 MB
__device__ int    g_sorted_si[NEDGE];
__device__ float4 g_sorted_exp[NEDGE];             // 12.8 MB
__device__ float  g_Vt[FIN * NH];

// ---------------- kernels ----------------

__global__ void zero_kernel() {
    int i = blockIdx.x * blockDim.x + threadIdx.x;
    int stride = gridDim.x * blockDim.x;
    for (int k = i; k < NNODE; k += stride) g_count[k] = 0;
}

// Vt[f,h] = sum_j Wt[f, h*32+j] * a_trg[h, j]
__global__ void fold_kernel(const float* __restrict__ Wt,
                            const float* __restrict__ a_trg) {
    int f = threadIdx.x;  // 128 threads
    #pragma unroll
    for (int h = 0; h < NH; h++) {
        float s = 0.0f;
        #pragma unroll
        for (int j = 0; j < 32; j++)
            s += Wt[f * COUT + h * 32 + j] * a_trg[h * 32 + j];
        g_Vt[f * NH + h] = s;
    }
}

// scores_trg = trg @ Vt   (warp per node)
__global__ void strg_kernel(const float* __restrict__ trg) {
    __shared__ float Vsh[FIN * NH];
    for (int i = threadIdx.x; i < FIN * NH; i += blockDim.x) Vsh[i] = g_Vt[i];
    __syncthreads();

    int gwarp = (blockIdx.x * blockDim.x + threadIdx.x) >> 5;
    int lane = threadIdx.x & 31;
    if (gwarp >= NNODE) return;

    float4 xv = ((const float4*)(trg + (size_t)gwarp * FIN))[lane];
    int f0 = lane * 4;
    float a0, a1, a2, a3;
    a0 = xv.x * Vsh[(f0+0)*4+0] + xv.y * Vsh[(f0+1)*4+0] + xv.z * Vsh[(f0+2)*4+0] + xv.w * Vsh[(f0+3)*4+0];
    a1 = xv.x * Vsh[(f0+0)*4+1] + xv.y * Vsh[(f0+1)*4+1] + xv.z * Vsh[(f0+2)*4+1] + xv.w * Vsh[(f0+3)*4+1];
    a2 = xv.x * Vsh[(f0+0)*4+2] + xv.y * Vsh[(f0+1)*4+2] + xv.z * Vsh[(f0+2)*4+2] + xv.w * Vsh[(f0+3)*4+2];
    a3 = xv.x * Vsh[(f0+0)*4+3] + xv.y * Vsh[(f0+1)*4+3] + xv.z * Vsh[(f0+2)*4+3] + xv.w * Vsh[(f0+3)*4+3];
    #pragma unroll
    for (int o = 16; o > 0; o >>= 1) {
        a0 += __shfl_xor_sync(0xffffffffu, a0, o);
        a1 += __shfl_xor_sync(0xffffffffu, a1, o);
        a2 += __shfl_xor_sync(0xffffffffu, a2, o);
        a3 += __shfl_xor_sync(0xffffffffu, a3, o);
    }
    if (lane == 0) g_scores_trg[gwarp] = make_float4(a0, a1, a2, a3);
}

// src_proj = src @ Ws (register-blocked: NPW nodes per warp iteration),
// fused scores_src epilogue.
__global__ void proj_kernel(const float* __restrict__ src,
                            const float* __restrict__ Ws,
                            const float* __restrict__ a_src) {
    extern __shared__ float sh[];
    float* Wsh = sh;                        // 128*128
    float* ash = Wsh + FIN * COUT;          // 128
    float* xsh = ash + COUT;                // PROJ_WARPS * NPW * FIN

    {
        const float4* w4 = (const float4*)Ws;
        float4* s4 = (float4*)Wsh;
        for (int i = threadIdx.x; i < FIN * COUT / 4; i += blockDim.x) s4[i] = w4[i];
        for (int i = threadIdx.x; i < COUT; i += blockDim.x) ash[i] = a_src[i];
    }
    __syncthreads();

    int lane = threadIdx.x & 31;
    int w = threadIdx.x >> 5;
    float* myx = xsh + w * (NPW * FIN);

    const int ngroups = NNODE / NPW;         // 6250 (exact)
    int group = blockIdx.x * PROJ_WARPS + w;
    int gstride = gridDim.x * PROJ_WARPS;

    for (int g = group; g < ngroups; g += gstride) {
        int n0 = g * NPW;
        #pragma unroll
        for (int r = 0; r < NPW; r++) {
            float4 xv = ((const float4*)(src + (size_t)(n0 + r) * FIN))[lane];
            ((float4*)(myx + r * FIN))[lane] = xv;
        }
        __syncwarp();

        float acc[NPW][4];
        #pragma unroll
        for (int r = 0; r < NPW; r++) { acc[r][0]=0.f; acc[r][1]=0.f; acc[r][2]=0.f; acc[r][3]=0.f; }

        #pragma unroll 4
        for (int f = 0; f < FIN; f++) {
            float4 wv = ((const float4*)(Wsh + f * COUT))[lane];
            #pragma unroll
            for (int r = 0; r < NPW; r++) {
                float xf = myx[r * FIN + f];
                acc[r][0] += xf * wv.x;
                acc[r][1] += xf * wv.y;
                acc[r][2] += xf * wv.z;
                acc[r][3] += xf * wv.w;
            }
        }

        int h = lane >> 3;
        int fi = (lane & 7) * 4;
        float c0 = ash[h * 32 + fi + 0];
        float c1 = ash[h * 32 + fi + 1];
        float c2 = ash[h * 32 + fi + 2];
        float c3 = ash[h * 32 + fi + 3];

        #pragma unroll
        for (int r = 0; r < NPW; r++) {
            int n = n0 + r;
            ((float4*)(g_src_proj + (size_t)n * COUT))[lane] =
                make_float4(acc[r][0], acc[r][1], acc[r][2], acc[r][3]);
            float p = acc[r][0]*c0 + acc[r][1]*c1 + acc[r][2]*c2 + acc[r][3]*c3;
            p += __shfl_xor_sync(0xffffffffu, p, 4);
            p += __shfl_xor_sync(0xffffffffu, p, 2);
            p += __shfl_xor_sync(0xffffffffu, p, 1);
            if ((lane & 7) == 0) ((float*)g_scores_src)[n * 4 + h] = p;
        }
        __syncwarp();
    }
}

__device__ __forceinline__ float lrelu_exp(float s) {
    float l = s > 0.0f ? s : 0.2f * s;
    return expf(l);
}

// pass 1: per-edge exp (stored), rank via count atomic
__global__ void edge1_kernel(const int* __restrict__ ei) {
    int e = blockIdx.x * blockDim.x + threadIdx.x;
    if (e >= NEDGE) return;
    int si = ei[e];
    int ti = ei[NEDGE + e];
    float4 ss = g_scores_src[si];
    float4 st = g_scores_trg[ti];
    float4 ex;
    ex.x = lrelu_exp(ss.x + st.x);
    ex.y = lrelu_exp(ss.y + st.y);
    ex.z = lrelu_exp(ss.z + st.z);
    ex.w = lrelu_exp(ss.w + st.w);
    g_edge_exp[e] = ex;
    g_edge_rank[e] = atomicAdd(&g_count[ti], 1);
}

// two-level scan: A) per-block inclusive scan, B) scan block sums, C) add carry
__global__ void scanA_kernel() {
    __shared__ int sh[SCAN_BLK];
    int tid = threadIdx.x;
    int gi = blockIdx.x * SCAN_BLK + tid;
    int v = (gi < NNODE) ? g_count[gi] : 0;
    sh[tid] = v;
    __syncthreads();
    #pragma unroll
    for (int off = 1; off < SCAN_BLK; off <<= 1) {
        int t = (tid >= off) ? sh[tid - off] : 0;
        __syncthreads();
        sh[tid] += t;
        __syncthreads();
    }
    if (gi < NNODE) g_offsets[gi + 1] = sh[tid];
    if (tid == SCAN_BLK - 1) g_blocksum[blockIdx.x] = sh[tid];
}

__global__ void scanB_kernel() {
    if (threadIdx.x == 0) {
        int c = 0;
        for (int b = 0; b < NSCAN_BLKS; b++) {
            g_blockcarry[b] = c;
            c += g_blocksum[b];
        }
        g_offsets[0] = 0;
    }
}

__global__ void scanC_kernel() {
    int tid = threadIdx.x;
    int gi = blockIdx.x * SCAN_BLK + tid;
    if (blockIdx.x == 0) return;  // carry 0
    if (gi < NNODE) g_offsets[gi + 1] += g_blockcarry[blockIdx.x];
}

// pass 2: pure permutation into CSR order
__global__ void edge2_kernel(const int* __restrict__ ei) {
    int e = blockIdx.x * blockDim.x + threadIdx.x;
    if (e >= NEDGE) return;
    int si = ei[e];
    int ti = ei[NEDGE + e];
    int pos = g_offsets[ti] + g_edge_rank[e];
    g_sorted_si[pos] = si;
    g_sorted_exp[pos] = g_edge_exp[e];
}

// aggregation: warp per target node; computes denom inline; 2x unrolled gather
__global__ void agg_kernel(float* __restrict__ out) {
    int gwarp = (blockIdx.x * blockDim.x + threadIdx.x) >> 5;
    int lane = threadIdx.x & 31;
    if (gwarp >= NNODE) return;

    int s = g_offsets[gwarp];
    int e2 = g_offsets[gwarp + 1];
    float a0 = 0.f, a1 = 0.f, a2 = 0.f, a3 = 0.f;
    float d0 = 0.f, d1 = 0.f, d2 = 0.f, d3 = 0.f;

    int i = s;
    for (; i + 1 < e2; i += 2) {
        int siA = g_sorted_si[i];
        int siB = g_sorted_si[i + 1];
        float4 exA = g_sorted_exp[i];
        float4 exB = g_sorted_exp[i + 1];
        const float* spA = g_src_proj + (size_t)siA * COUT;
        const float* spB = g_src_proj + (size_t)siB * COUT;
        float vA0 = spA[lane], vA1 = spA[32+lane], vA2 = spA[64+lane], vA3 = spA[96+lane];
        float vB0 = spB[lane], vB1 = spB[32+lane], vB2 = spB[64+lane], vB3 = spB[96+lane];
        a0 += exA.x * vA0 + exB.x * vB0;
        a1 += exA.y * vA1 + exB.y * vB1;
        a2 += exA.z * vA2 + exB.z * vB2;
        a3 += exA.w * vA3 + exB.w * vB3;
        d0 += exA.x + exB.x;
        d1 += exA.y + exB.y;
        d2 += exA.z + exB.z;
        d3 += exA.w + exB.w;
    }
    if (i < e2) {
        int si = g_sorted_si[i];
        float4 ex = g_sorted_exp[i];
        const float* sp = g_src_proj + (size_t)si * COUT;
        a0 += ex.x * sp[lane];
        a1 += ex.y * sp[32 + lane];
        a2 += ex.z * sp[64 + lane];
        a3 += ex.w * sp[96 + lane];
        d0 += ex.x; d1 += ex.y; d2 += ex.z; d3 += ex.w;
    }

    float r0 = 1.0f / (d0 + 1e-16f);
    float r1 = 1.0f / (d1 + 1e-16f);
    float r2 = 1.0f / (d2 + 1e-16f);
    float r3 = 1.0f / (d3 + 1e-16f);

    float* o = out + (size_t)gwarp * COUT;
    o[lane]      = a0 * r0;
    o[32 + lane] = a1 * r1;
    o[64 + lane] = a2 * r2;
    o[96 + lane] = a3 * r3;
}

// ---------------- launch ----------------

extern "C" void kernel_launch(void* const* d_in, const int* in_sizes, int n_in,
                              void* d_out, int out_size) {
    const float* trg   = (const float*)d_in[0];
    const float* src   = (const float*)d_in[1];
    const int*   ei    = (const int*)d_in[2];
    const float* Wt    = (const float*)d_in[3];
    const float* Ws    = (const float*)d_in[4];
    const float* a_src = (const float*)d_in[5];
    const float* a_trg = (const float*)d_in[6];
    float* out = (float*)d_out;

    const int PROJ_BLOCK = PROJ_WARPS * 32;  // 256
    size_t proj_smem = (size_t)(FIN * COUT + COUT + PROJ_WARPS * NPW * FIN) * sizeof(float);
    cudaFuncSetAttribute(proj_kernel, cudaFuncAttributeMaxDynamicSharedMemorySize,
                         (int)proj_smem);

    zero_kernel<<<64, 256>>>();
    fold_kernel<<<1, 128>>>(Wt, a_trg);

    {
        int blocks = (NNODE * 32 + 255) / 256;
        strg_kernel<<<blocks, 256>>>(trg);
    }

    proj_kernel<<<296, PROJ_BLOCK, proj_smem>>>(src, Ws, a_src);

    {
        int blocks = (NEDGE + 255) / 256;
        edge1_kernel<<<blocks, 256>>>(ei);
    }

    scanA_kernel<<<NSCAN_BLKS, SCAN_BLK>>>();
    scanB_kernel<<<1, 32>>>();
    scanC_kernel<<<NSCAN_BLKS, SCAN_BLK>>>();

    {
        int blocks = (NEDGE + 255) / 256;
        edge2_kernel<<<blocks, 256>>>(ei);
    }

    {
        int blocks = (NNODE * 32 + 255) / 256;
        agg_kernel<<<blocks, 256>>>(out);
    }
}